// round 1
// baseline (speedup 1.0000x reference)
#include <cuda_runtime.h>
#include <math.h>

// ---------------------------------------------------------------------------
// YOLOv4 loss, 3 scales. Key insight: box/cls channels only matter at the
// <=800 positive cells per scale; conf channel (ch 4) matters everywhere.
// So: tiny positives kernel + strided conf-gather kernel + finalize.
// ---------------------------------------------------------------------------

#define NB 16       // batch
#define NT 50       // targets per image
#define NA 3        // anchors per scale
#define NC 80       // classes
#define CH 85       // 5 + NC
#define IMGF 608.0f

__device__ float g_acc[3][5];   // [scale]{npos, coord_sum, confpos_sum, confneg_corr, cls_sum}
__device__ float g_negsum[3];   // sum over ALL cells of -log1p(-p)

__constant__ float c_anch[3][3][2] = {
    {{12.f,16.f},{19.f,36.f},{40.f,28.f}},
    {{36.f,75.f},{76.f,55.f},{72.f,146.f}},
    {{142.f,110.f},{192.f,243.f},{459.f,401.f}}
};
__constant__ int c_hw[3] = {76, 38, 19};

__device__ __forceinline__ float clip01(float x) { return fminf(fmaxf(x, 0.f), 1.f); }
__device__ __forceinline__ float sigmoidf_(float x) { return 1.f / (1.f + expf(-x)); }
__device__ __forceinline__ float clip_p(float p) {
    return fminf(fmaxf(p, 1e-10f), 1.0f - 1e-10f);
}

// IoU on (cx,cy,w,h) boxes, matching the jnp formula incl. EPS
__device__ __forceinline__ float iou_f(float cx1, float cy1, float w1, float h1,
                                       float cx2, float cy2, float w2, float h2) {
    float b1x1 = cx1 - w1 * 0.5f, b1y1 = cy1 - h1 * 0.5f;
    float b1x2 = cx1 + w1 * 0.5f, b1y2 = cy1 + h1 * 0.5f;
    float b2x1 = cx2 - w2 * 0.5f, b2y1 = cy2 - h2 * 0.5f;
    float b2x2 = cx2 + w2 * 0.5f, b2y2 = cy2 + h2 * 0.5f;
    float iw = fmaxf(fminf(b1x2, b2x2) - fmaxf(b1x1, b2x1), 0.f);
    float ih = fmaxf(fminf(b1y2, b2y2) - fmaxf(b1y1, b2y1), 0.f);
    float inter = iw * ih;
    float uni = (b1x2 - b1x1) * (b1y2 - b1y1) + (b2x2 - b2x1) * (b2y2 - b2y1) - inter + 1e-7f;
    return inter / uni;
}

// ---------------------------------------------------------------------------
__global__ void k_zero() {
    int i = threadIdx.x;
    if (i < 15) ((float*)g_acc)[i] = 0.f;
    if (i < 3)  g_negsum[i] = 0.f;
}

// ---------------------------------------------------------------------------
// One block per (batch b, scale s). Threads 0..49 decode targets into shared;
// then 4 warps iterate targets: dedup (last-write-wins) + positive-cell loss.
__global__ void k_pos(const float* __restrict__ p0, const float* __restrict__ p1,
                      const float* __restrict__ p2, const float* __restrict__ tgt) {
    const int b = blockIdx.x;
    const int s = blockIdx.y;
    const int HW = c_hw[s];
    const float* __restrict__ pred = (s == 0) ? p0 : ((s == 1) ? p1 : p2);

    __shared__ int   sbest[NT], sgx[NT], sgy[NT], sval[NT];
    __shared__ float sbox[NT][4];

    const int tid  = threadIdx.x;
    const int warp = tid >> 5;
    const int lane = tid & 31;

    if (tid < NT) {
        const float* tr = tgt + (size_t)(b * NT + tid) * CH;
        float x = clip01(tr[0]), y = clip01(tr[1]);
        float w = clip01(tr[2]), h = clip01(tr[3]);
        sbox[tid][0] = x; sbox[tid][1] = y; sbox[tid][2] = w; sbox[tid][3] = h;
        sval[tid] = (tr[4] > 0.f) ? 1 : 0;
        // best anchor: strict '>' first-max argmax of IoU(abox, gtbox)
        float biou = -1.f; int best = 0;
        #pragma unroll
        for (int a = 0; a < NA; a++) {
            float aw = c_anch[s][a][0] / IMGF;
            float ah = c_anch[s][a][1] / IMGF;
            float io = iou_f(0.5f, 0.5f, aw, ah, x, y, w, h);
            if (io > biou) { biou = io; best = a; }
        }
        sbest[tid] = best;
        int gx = (int)(x * (float)HW);  // truncation == .astype(int32) for x>=0
        int gy = (int)(y * (float)HW);
        sgx[tid] = min(max(gx, 0), HW - 1);
        sgy[tid] = min(max(gy, 0), HW - 1);
    }
    __syncthreads();

    for (int t = warp; t < NT; t += 4) {
        const int valid = sval[t];
        // last-write-wins: keep iff no later valid target in same batch hits same cell
        int conflict = 0;
        if (valid) {
            for (int j = t + 1 + lane; j < NT; j += 32) {
                if (sval[j] && sbest[j] == sbest[t] && sgx[j] == sgx[t] && sgy[j] == sgy[t])
                    conflict = 1;
            }
        }
        unsigned any = __ballot_sync(0xffffffffu, conflict);
        if (!valid || any) continue;

        const int a = sbest[t], gx = sgx[t], gy = sgy[t];
        const float* cell = pred + ((((size_t)b * NA + a) * HW + gy) * HW + gx) * CH;
        const float* trow = tgt + (size_t)(b * NT + t) * CH;

        // class BCE (warp-parallel over 80 classes)
        float csum = 0.f;
        for (int c = lane; c < NC; c += 32) {
            float pc = clip_p(sigmoidf_(cell[5 + c]));
            float tc = clip01(trow[5 + c]);
            csum -= tc * logf(pc) + (1.f - tc) * log1pf(-pc);
        }
        #pragma unroll
        for (int o = 16; o > 0; o >>= 1) csum += __shfl_down_sync(0xffffffffu, csum, o);

        if (lane == 0) {
            float Wf = (float)HW;
            float px = clip01((sigmoidf_(cell[0]) + (float)gx) / Wf);
            float py = clip01((sigmoidf_(cell[1]) + (float)gy) / Wf);
            float tw = fminf(fmaxf(cell[2], -10.f), 10.f);
            float th = fminf(fmaxf(cell[3], -10.f), 10.f);
            float pw = clip01(expf(tw) * c_anch[s][a][0] / IMGF);
            float ph = clip01(expf(th) * c_anch[s][a][1] / IMGF);
            float io = iou_f(px, py, pw, ph, sbox[t][0], sbox[t][1], sbox[t][2], sbox[t][3]);
            float p  = clip_p(sigmoidf_(cell[4]));
            atomicAdd(&g_acc[s][0], 1.f);
            atomicAdd(&g_acc[s][1], 1.f - io);
            atomicAdd(&g_acc[s][2], -logf(p));
            atomicAdd(&g_acc[s][3], -log1pf(-p));   // correction for negsum double-count
            atomicAdd(&g_acc[s][4], csum);
        }
    }
}

// ---------------------------------------------------------------------------
// All-cells conf: thread per cell, loads only channel 4 (stride 85 gather).
__global__ void k_conf(const float* __restrict__ p0, const float* __restrict__ p1,
                       const float* __restrict__ p2) {
    const int s = blockIdx.y;
    const int HW = c_hw[s];
    const int N = NB * NA * HW * HW;
    const int idx = blockIdx.x * blockDim.x + threadIdx.x;
    if (blockIdx.x * blockDim.x >= N) return;   // whole block out of range for this scale
    const float* __restrict__ pred = (s == 0) ? p0 : ((s == 1) ? p1 : p2);

    float v = 0.f;
    if (idx < N) {
        float x = pred[(size_t)idx * CH + 4];
        float p = clip_p(sigmoidf_(x));
        v = -log1pf(-p);
    }

    // block reduce
    #pragma unroll
    for (int o = 16; o > 0; o >>= 1) v += __shfl_down_sync(0xffffffffu, v, o);
    __shared__ float red[8];
    const int lane = threadIdx.x & 31, warp = threadIdx.x >> 5;
    if (lane == 0) red[warp] = v;
    __syncthreads();
    if (warp == 0) {
        v = (lane < (blockDim.x >> 5)) ? red[lane] : 0.f;
        #pragma unroll
        for (int o = 4; o > 0; o >>= 1) v += __shfl_down_sync(0xffffffffu, v, o);
        if (lane == 0) atomicAdd(&g_negsum[s], v);
    }
}

// ---------------------------------------------------------------------------
__global__ void k_fin(float* __restrict__ out) {
    if (threadIdx.x != 0 || blockIdx.x != 0) return;
    float coord = 0.f, conf = 0.f, cls = 0.f;
    #pragma unroll
    for (int s = 0; s < 3; s++) {
        float HW = (float)c_hw[s];
        float ncells = (float)NB * NA * HW * HW;
        float npos = g_acc[s][0];
        float nneg = ncells - npos;
        float dn = fmaxf(npos, 1.f);
        if (npos > 0.f) coord += g_acc[s][1] / dn;
        conf += g_acc[s][2] / dn + 0.5f * (g_negsum[s] - g_acc[s][3]) / fmaxf(nneg, 1.f);
        if (npos > 0.f) cls += g_acc[s][4] / fmaxf(npos * (float)NC, 1.f);
    }
    out[0] = 5.f * coord + conf + 1.f * cls;
    out[1] = coord;
    out[2] = conf;
    out[3] = cls;
}

// ---------------------------------------------------------------------------
extern "C" void kernel_launch(void* const* d_in, const int* in_sizes, int n_in,
                              void* d_out, int out_size) {
    // Identify inputs by element count (robust to metadata ordering).
    const float *p0 = nullptr, *p1 = nullptr, *p2 = nullptr, *tg = nullptr;
    for (int i = 0; i < n_in; i++) {
        switch (in_sizes[i]) {
            case NB * NA * 76 * 76 * CH: p0 = (const float*)d_in[i]; break;
            case NB * NA * 38 * 38 * CH: p1 = (const float*)d_in[i]; break;
            case NB * NA * 19 * 19 * CH: p2 = (const float*)d_in[i]; break;
            case NB * NT * CH:           tg = (const float*)d_in[i]; break;
            default: break;
        }
    }
    float* out = (float*)d_out;

    k_zero<<<1, 32>>>();

    dim3 gp(NB, 3);
    k_pos<<<gp, 128>>>(p0, p1, p2, tg);

    const int N0 = NB * NA * 76 * 76;
    dim3 gc((N0 + 255) / 256, 3);
    k_conf<<<gc, 256>>>(p0, p1, p2);

    k_fin<<<1, 32>>>(out);
    (void)out_size;
}

// round 2
// speedup vs baseline: 1.5920x; 1.5920x over previous
#include <cuda_runtime.h>
#include <math.h>

// ---------------------------------------------------------------------------
// YOLOv4 loss, 3 scales, SINGLE kernel launch.
//   blocks [0,48):   positives (batch b = blk&15, scale s = blk>>4)
//   blocks [48,...): conf-channel gather, 4 cells/thread, per-scale ranges
//   last block to finish: finalize + write out + reset state for next replay
// ---------------------------------------------------------------------------

#define NB 16
#define NT 50
#define NA 3
#define NC 80
#define CH 85
#define IMGF 608.0f

#define CELLS0 (NB * NA * 76 * 76)   // 277248
#define CELLS1 (NB * NA * 38 * 38)   // 69312
#define CELLS2 (NB * NA * 19 * 19)   // 17328
#define CPB 1024                      // cells per conf block (256 thr * 4)
#define CB0 ((CELLS0 + CPB - 1) / CPB)  // 271
#define CB1 ((CELLS1 + CPB - 1) / CPB)  // 68
#define CB2 ((CELLS2 + CPB - 1) / CPB)  // 17
#define NPOSBLK (NB * NA)               // 48
#define NBLK (NPOSBLK + CB0 + CB1 + CB2)

// zero-initialized at module load; reset by the last block each invocation
__device__ float    g_acc[3][5];   // {npos, coord, confpos, confneg_corr, cls}
__device__ float    g_negsum[3];
__device__ unsigned g_cnt;

__constant__ float c_anch[3][3][2] = {
    {{12.f,16.f},{19.f,36.f},{40.f,28.f}},
    {{36.f,75.f},{76.f,55.f},{72.f,146.f}},
    {{142.f,110.f},{192.f,243.f},{459.f,401.f}}
};
__constant__ int c_hw[3] = {76, 38, 19};

__device__ __forceinline__ float clip01(float x) { return fminf(fmaxf(x, 0.f), 1.f); }
__device__ __forceinline__ float sigmoidf_(float x) { return 1.f / (1.f + expf(-x)); }
__device__ __forceinline__ float clip_p(float p) {
    return fminf(fmaxf(p, 1e-10f), 1.0f - 1e-10f);
}

__device__ __forceinline__ float iou_f(float cx1, float cy1, float w1, float h1,
                                       float cx2, float cy2, float w2, float h2) {
    float b1x1 = cx1 - w1 * 0.5f, b1y1 = cy1 - h1 * 0.5f;
    float b1x2 = cx1 + w1 * 0.5f, b1y2 = cy1 + h1 * 0.5f;
    float b2x1 = cx2 - w2 * 0.5f, b2y1 = cy2 - h2 * 0.5f;
    float b2x2 = cx2 + w2 * 0.5f, b2y2 = cy2 + h2 * 0.5f;
    float iw = fmaxf(fminf(b1x2, b2x2) - fmaxf(b1x1, b2x1), 0.f);
    float ih = fmaxf(fminf(b1y2, b2y2) - fmaxf(b1y1, b2y1), 0.f);
    float inter = iw * ih;
    float uni = (b1x2 - b1x1) * (b1y2 - b1y1) + (b2x2 - b2x1) * (b2y2 - b2y1) - inter + 1e-7f;
    return inter / uni;
}

__global__ __launch_bounds__(256) void k_fused(
    const float* __restrict__ p0, const float* __restrict__ p1,
    const float* __restrict__ p2, const float* __restrict__ tgt,
    float* __restrict__ out)
{
    const int tid  = threadIdx.x;
    const int lane = tid & 31;
    const int warp = tid >> 5;
    const int blk  = blockIdx.x;

    if (blk < NPOSBLK) {
        // ------------------ positives: one block per (b, s) ------------------
        const int b = blk & 15;
        const int s = blk >> 4;
        const int HW = c_hw[s];
        const float* __restrict__ pred = (s == 0) ? p0 : ((s == 1) ? p1 : p2);

        __shared__ int   sbest[NT], sgx[NT], sgy[NT], sval[NT];
        __shared__ float sbox[NT][4];

        if (tid < NT) {
            const float* tr = tgt + (size_t)(b * NT + tid) * CH;
            float x = clip01(tr[0]), y = clip01(tr[1]);
            float w = clip01(tr[2]), h = clip01(tr[3]);
            sbox[tid][0] = x; sbox[tid][1] = y; sbox[tid][2] = w; sbox[tid][3] = h;
            sval[tid] = (tr[4] > 0.f) ? 1 : 0;
            float biou = -1.f; int best = 0;
            #pragma unroll
            for (int a = 0; a < NA; a++) {
                float aw = c_anch[s][a][0] / IMGF;
                float ah = c_anch[s][a][1] / IMGF;
                float io = iou_f(0.5f, 0.5f, aw, ah, x, y, w, h);
                if (io > biou) { biou = io; best = a; }
            }
            sbest[tid] = best;
            int gx = (int)(x * (float)HW);
            int gy = (int)(y * (float)HW);
            sgx[tid] = min(max(gx, 0), HW - 1);
            sgy[tid] = min(max(gy, 0), HW - 1);
        }
        __syncthreads();

        // per-block partial accumulators in shared, one atomic flush at end
        __shared__ float sacc[5];
        if (tid < 5) sacc[tid] = 0.f;
        __syncthreads();

        for (int t = warp; t < NT; t += 8) {
            const int valid = sval[t];
            int conflict = 0;
            if (valid) {
                for (int j = t + 1 + lane; j < NT; j += 32) {
                    if (sval[j] && sbest[j] == sbest[t] && sgx[j] == sgx[t] && sgy[j] == sgy[t])
                        conflict = 1;
                }
            }
            unsigned any = __ballot_sync(0xffffffffu, conflict);
            if (!valid || any) continue;

            const int a = sbest[t], gx = sgx[t], gy = sgy[t];
            const float* cell = pred + ((((size_t)b * NA + a) * HW + gy) * HW + gx) * CH;
            const float* trow = tgt + (size_t)(b * NT + t) * CH;

            float csum = 0.f;
            #pragma unroll
            for (int k = 0; k < 3; k++) {
                int c = lane + 32 * k;
                if (c < NC) {
                    float pc = clip_p(sigmoidf_(cell[5 + c]));
                    float tc = clip01(trow[5 + c]);
                    csum -= tc * logf(pc) + (1.f - tc) * log1pf(-pc);
                }
            }
            #pragma unroll
            for (int o = 16; o > 0; o >>= 1) csum += __shfl_down_sync(0xffffffffu, csum, o);

            if (lane == 0) {
                float Wf = (float)HW;
                float px = clip01((sigmoidf_(cell[0]) + (float)gx) / Wf);
                float py = clip01((sigmoidf_(cell[1]) + (float)gy) / Wf);
                float tw = fminf(fmaxf(cell[2], -10.f), 10.f);
                float th = fminf(fmaxf(cell[3], -10.f), 10.f);
                float pw = clip01(expf(tw) * c_anch[s][a][0] / IMGF);
                float ph = clip01(expf(th) * c_anch[s][a][1] / IMGF);
                float io = iou_f(px, py, pw, ph, sbox[t][0], sbox[t][1], sbox[t][2], sbox[t][3]);
                float p  = clip_p(sigmoidf_(cell[4]));
                atomicAdd(&sacc[0], 1.f);
                atomicAdd(&sacc[1], 1.f - io);
                atomicAdd(&sacc[2], -logf(p));
                atomicAdd(&sacc[3], -log1pf(-p));
                atomicAdd(&sacc[4], csum);
            }
        }
        __syncthreads();
        if (tid < 5 && sacc[tid] != 0.f) atomicAdd(&g_acc[s][tid], sacc[tid]);

    } else {
        // ------------------ conf gather: 4 cells/thread ------------------
        int cid = blk - NPOSBLK;
        int s, blkInS;
        if (cid < CB0)            { s = 0; blkInS = cid; }
        else if (cid < CB0 + CB1) { s = 1; blkInS = cid - CB0; }
        else                      { s = 2; blkInS = cid - CB0 - CB1; }
        const int N = (s == 0) ? CELLS0 : ((s == 1) ? CELLS1 : CELLS2);
        const float* __restrict__ pred = (s == 0) ? p0 : ((s == 1) ? p1 : p2);

        const int base = blkInS * CPB + tid;
        float v = 0.f;
        #pragma unroll
        for (int k = 0; k < 4; k++) {
            int idx = base + k * 256;
            if (idx < N) {
                float x = __ldg(pred + (size_t)idx * CH + 4);
                float p = clip_p(sigmoidf_(x));
                v -= log1pf(-p);
            }
        }
        #pragma unroll
        for (int o = 16; o > 0; o >>= 1) v += __shfl_down_sync(0xffffffffu, v, o);
        __shared__ float red[8];
        if (lane == 0) red[warp] = v;
        __syncthreads();
        if (warp == 0) {
            v = (lane < 8) ? red[lane] : 0.f;
            #pragma unroll
            for (int o = 4; o > 0; o >>= 1) v += __shfl_down_sync(0xffffffffu, v, o);
            if (lane == 0) atomicAdd(&g_negsum[s], v);
        }
    }

    // ------------------ last block: finalize + reset ------------------
    __shared__ int isLast;
    __syncthreads();
    if (tid == 0) {
        __threadfence();
        unsigned c = atomicAdd(&g_cnt, 1u);
        isLast = (c == (unsigned)(NBLK - 1));
    }
    __syncthreads();
    if (isLast && tid == 0) {
        float coord = 0.f, conf = 0.f, cls = 0.f;
        #pragma unroll
        for (int s = 0; s < 3; s++) {
            float HW = (float)c_hw[s];
            float ncells = (float)NB * NA * HW * HW;
            float npos = g_acc[s][0];
            float nneg = ncells - npos;
            float dn = fmaxf(npos, 1.f);
            if (npos > 0.f) coord += g_acc[s][1] / dn;
            conf += g_acc[s][2] / dn + 0.5f * (g_negsum[s] - g_acc[s][3]) / fmaxf(nneg, 1.f);
            if (npos > 0.f) cls += g_acc[s][4] / fmaxf(npos * (float)NC, 1.f);
        }
        out[0] = 5.f * coord + conf + cls;
        out[1] = coord;
        out[2] = conf;
        out[3] = cls;
        // reset state so the next graph replay starts identically
        #pragma unroll
        for (int i = 0; i < 15; i++) ((float*)g_acc)[i] = 0.f;
        g_negsum[0] = g_negsum[1] = g_negsum[2] = 0.f;
        __threadfence();
        g_cnt = 0u;
    }
}

extern "C" void kernel_launch(void* const* d_in, const int* in_sizes, int n_in,
                              void* d_out, int out_size) {
    const float *p0 = nullptr, *p1 = nullptr, *p2 = nullptr, *tg = nullptr;
    for (int i = 0; i < n_in; i++) {
        switch (in_sizes[i]) {
            case NB * NA * 76 * 76 * CH: p0 = (const float*)d_in[i]; break;
            case NB * NA * 38 * 38 * CH: p1 = (const float*)d_in[i]; break;
            case NB * NA * 19 * 19 * CH: p2 = (const float*)d_in[i]; break;
            case NB * NT * CH:           tg = (const float*)d_in[i]; break;
            default: break;
        }
    }
    k_fused<<<NBLK, 256>>>(p0, p1, p2, tg, (float*)d_out);
    (void)out_size;
}